// round 13
// baseline (speedup 1.0000x reference)
#include <cuda_runtime.h>
#include <cuda_bf16.h>
#include <cuda_fp16.h>
#include <math.h>
#include <float.h>
#include <stdint.h>

#define N_NODES 50000
#define N_EDGES 800000
#define DIM 128
#define EDIM 32
#define NB_SCAN ((N_NODES + 1023) / 1024)   // 49 scan blocks

// ---------------- scratch (static device allocations) ----------------
__device__ __half g_zh[N_NODES * DIM];    // projected features (fp16 for gather BW)
__device__ float g_ssrc[N_NODES];
__device__ float g_sdst[N_NODES];
__device__ int   g_cnt[N_NODES];          // zero-init at load; scan1 restores zeros
__device__ int   g_lex[N_NODES];          // block-local exclusive scan
__device__ int   g_bsum[64];
__device__ int   g_off[N_NODES + 1];
__device__ int   g_cur[N_NODES];
__device__ uint2 g_pair[N_EDGES];         // (src, bits(t)) permuted into CSR-by-dst order

// ============ manual mma.sync bf16 GEMM: z = nfeats @ W_fc^T ==================
// 2-split, 3 passes (AhWh + AhWl + AlWh), fp32 accum; z stored fp16.
// Block: 256 threads (8 warps) = 64 rows x 128 cols. Warp w: n0 = w*16.
#define APAD 136           // bf16 row pad (272B rows: conflict-free ldmatrix)
#define WPAD 136
#define ZPAD 132           // f32 row pad for epilogue tile
#define SMG_AH   0
#define SMG_AL   17408                          // 64*136*2
#define SMG_WH   34816
#define SMG_WL   (34816 + 34816)                // 69632  (128*136*2 each)
#define SMG_ATTN 104448
#define SMG_TOTAL (SMG_ATTN + 256 * 4)          // 105472
#define SMG_ZT   0                              // f32 z tile overlays A after MMA

#define LDSM4(R, addr) \
    asm volatile("ldmatrix.sync.aligned.m8n8.x4.shared.b16 {%0,%1,%2,%3}, [%4];" \
        : "=r"((R)[0]), "=r"((R)[1]), "=r"((R)[2]), "=r"((R)[3]) : "r"(addr))

#define MMA_BF16(C, AR, B0, B1) \
    asm volatile("mma.sync.aligned.m16n8k16.row.col.f32.bf16.bf16.f32 " \
        "{%0,%1,%2,%3}, {%4,%5,%6,%7}, {%8,%9}, {%0,%1,%2,%3};" \
        : "+f"((C)[0]), "+f"((C)[1]), "+f"((C)[2]), "+f"((C)[3]) \
        : "r"((AR)[0]), "r"((AR)[1]), "r"((AR)[2]), "r"((AR)[3]), "r"(B0), "r"(B1))

__device__ __forceinline__ void split_store(__nv_bfloat16* sh, __nv_bfloat16* sl,
                                            int off, float4 v) {
    float f[4] = {v.x, v.y, v.z, v.w};
    uint16_t hh[4], ll[4];
#pragma unroll
    for (int q = 0; q < 4; q++) {
        __nv_bfloat16 h = __float2bfloat16(f[q]);
        hh[q] = __bfloat16_as_ushort(h);
        ll[q] = __bfloat16_as_ushort(__float2bfloat16(f[q] - __bfloat162float(h)));
    }
    *(uint2*)&sh[off] = make_uint2((uint32_t)hh[0] | ((uint32_t)hh[1] << 16),
                                   (uint32_t)hh[2] | ((uint32_t)hh[3] << 16));
    *(uint2*)&sl[off] = make_uint2((uint32_t)ll[0] | ((uint32_t)ll[1] << 16),
                                   (uint32_t)ll[2] | ((uint32_t)ll[3] << 16));
}

__global__ void __launch_bounds__(256) gemm_mma_kernel(const float* __restrict__ A,
                                                       const float* __restrict__ W,
                                                       const float* __restrict__ Wattn) {
    extern __shared__ char smem[];
    __nv_bfloat16* sAh = (__nv_bfloat16*)(smem + SMG_AH);
    __nv_bfloat16* sAl = (__nv_bfloat16*)(smem + SMG_AL);
    __nv_bfloat16* sWh = (__nv_bfloat16*)(smem + SMG_WH);
    __nv_bfloat16* sWl = (__nv_bfloat16*)(smem + SMG_WL);
    float* szt  = (float*)(smem + SMG_ZT);
    float* asrc = (float*)(smem + SMG_ATTN);
    float* adst = asrc + 128;

    int tid = threadIdx.x;
    int wid = tid >> 5, lane = tid & 31;
    int i0 = blockIdx.x * 64;
    int n0 = wid * 16;

    if (tid < 128) {
        asrc[tid] = Wattn[tid];
        adst[tid] = Wattn[DIM + EDIM + tid];
    }

    // stage W fp32 -> split bf16 hi/lo into smem (W is L2-hot, 64 KB)
#pragma unroll
    for (int t = 0; t < 16; t++) {
        int idx = tid + t * 256;            // 4096 float4
        int row = idx >> 5, col = (idx & 31) * 4;
        float4 wv = *(const float4*)&W[row * 128 + col];
        split_store(sWh, sWl, row * WPAD + col, wv);
    }

    // load A 64x128 fp32, split to bf16 hi/lo in smem
#pragma unroll
    for (int t = 0; t < 8; t++) {
        int idx = tid + t * 256;            // 2048 float4
        int row = idx >> 5, col = (idx & 31) * 4;
        int gr = i0 + row;
        float4 av = make_float4(0.f, 0.f, 0.f, 0.f);
        if (gr < N_NODES) av = *(const float4*)&A[gr * 128 + col];
        split_store(sAh, sAl, row * APAD + col, av);
    }
    __syncthreads();

    uint32_t sb = (uint32_t)__cvta_generic_to_shared(smem);
    uint32_t aoff = (uint32_t)(((lane & 15) * APAD + (lane >> 4) * 8) * 2);
    uint32_t aH = sb + SMG_AH + aoff;
    uint32_t aL = sb + SMG_AL + aoff;
    uint32_t boff = (uint32_t)(((n0 + ((lane >> 4) << 3) + (lane & 7)) * WPAD
                                + (((lane >> 3) & 1) << 3)) * 2);
    uint32_t bH = sb + SMG_WH + boff;
    uint32_t bL = sb + SMG_WL + boff;

    float c[4][2][4];
#pragma unroll
    for (int m = 0; m < 4; m++)
#pragma unroll
        for (int g = 0; g < 2; g++)
#pragma unroll
            for (int q = 0; q < 4; q++) c[m][g][q] = 0.f;

#pragma unroll
    for (int pass = 0; pass < 3; pass++) {
        uint32_t ab = (pass == 2) ? aL : aH;
        uint32_t bb = (pass == 1) ? bL : bH;
#pragma unroll
        for (int k = 0; k < 8; k++) {
            uint32_t br[4];
            LDSM4(br, bb + k * 32);
#pragma unroll
            for (int m = 0; m < 4; m++) {
                uint32_t ar[4];
                LDSM4(ar, ab + (uint32_t)((m * 16 * APAD + k * 16) * 2));
                MMA_BF16(c[m][0], ar, br[0], br[1]);
                MMA_BF16(c[m][1], ar, br[2], br[3]);
            }
        }
    }

    __syncthreads();   // all warps done reading sA before z-tile overlay

#pragma unroll
    for (int m = 0; m < 4; m++)
#pragma unroll
        for (int g = 0; g < 2; g++) {
            int row = m * 16 + (lane >> 2);
            int col = n0 + g * 8 + (lane & 3) * 2;
            *(float2*)&szt[row * ZPAD + col] = make_float2(c[m][g][0], c[m][g][1]);
            *(float2*)&szt[(row + 8) * ZPAD + col] = make_float2(c[m][g][2], c[m][g][3]);
        }
    __syncthreads();

    // s_src / s_dst: thread t -> row t>>2, quarter t&3 (32 cols), 4-lane reduce
    {
        int r = tid >> 2, q = tid & 3;
        const float* zr = szt + r * ZPAD + q * 32;
        float ps = 0.f, pd = 0.f;
#pragma unroll
        for (int cc = 0; cc < 32; cc++) {
            float v = zr[cc];
            ps += v * asrc[q * 32 + cc];
            pd += v * adst[q * 32 + cc];
        }
        ps += __shfl_xor_sync(0xffffffffu, ps, 1);
        pd += __shfl_xor_sync(0xffffffffu, pd, 1);
        ps += __shfl_xor_sync(0xffffffffu, ps, 2);
        pd += __shfl_xor_sync(0xffffffffu, pd, 2);
        int gr = i0 + r;
        if (q == 0 && gr < N_NODES) { g_ssrc[gr] = ps; g_sdst[gr] = pd; }
    }

    // coalesced fp16 z store
#pragma unroll
    for (int t = 0; t < 8; t++) {
        int idx = tid + t * 256;
        int row = idx >> 5, col = (idx & 31) * 4;
        int gr = i0 + row;
        if (gr < N_NODES) {
            float4 v = *(const float4*)&szt[row * ZPAD + col];
            __half2 p0 = __floats2half2_rn(v.x, v.y);
            __half2 p1 = __floats2half2_rn(v.z, v.w);
            uint2 pk;
            pk.x = *(uint32_t*)&p0;
            pk.y = *(uint32_t*)&p1;
            *(uint2*)&g_zh[gr * 128 + col] = pk;
        }
    }
}

// ---------------- histogram of dst (8 edges per thread, RED fire-and-forget) --
__global__ __launch_bounds__(256) void hist_kernel(const int* __restrict__ dst) {
    int i = blockIdx.x * blockDim.x + threadIdx.x;
    int base = i * 8;
    if (base < N_EDGES) {
        int4 a = *(const int4*)&dst[base];
        int4 b = *(const int4*)&dst[base + 4];
        atomicAdd(&g_cnt[a.x], 1);
        atomicAdd(&g_cnt[a.y], 1);
        atomicAdd(&g_cnt[a.z], 1);
        atomicAdd(&g_cnt[a.w], 1);
        atomicAdd(&g_cnt[b.x], 1);
        atomicAdd(&g_cnt[b.y], 1);
        atomicAdd(&g_cnt[b.z], 1);
        atomicAdd(&g_cnt[b.w], 1);
    }
}

// ---------------- parallel scan, phase 1 (self-restoring: zeroes g_cnt) ------
__global__ __launch_bounds__(1024) void scan1_kernel() {
    __shared__ int ws[32];
    int t = threadIdx.x, b = blockIdx.x;
    int i = b * 1024 + t;
    int lane = t & 31, w = t >> 5;
    int c = (i < N_NODES) ? g_cnt[i] : 0;
    if (i < N_NODES) g_cnt[i] = 0;     // restore zeros for the next graph replay
    int v = c;
#pragma unroll
    for (int o = 1; o < 32; o <<= 1) {
        int n = __shfl_up_sync(0xffffffffu, v, o);
        if (lane >= o) v += n;
    }
    if (lane == 31) ws[w] = v;
    __syncthreads();
    if (w == 0) {
        int s = ws[lane];
#pragma unroll
        for (int o = 1; o < 32; o <<= 1) {
            int n = __shfl_up_sync(0xffffffffu, s, o);
            if (lane >= o) s += n;
        }
        ws[lane] = s;
    }
    __syncthreads();
    int pre = (w > 0) ? ws[w - 1] : 0;
    if (i < N_NODES) g_lex[i] = pre + v - c;
    if (t == 0) g_bsum[b] = ws[31];
}

// ---------------- phase 2+3 merged ----------------
__global__ __launch_bounds__(256) void scan23_kernel() {
    __shared__ int sb[64];
    int t = threadIdx.x;
    if (t < 64) {
        int v = (t < NB_SCAN) ? g_bsum[t] : 0;
        sb[t] = v;
    }
    __syncthreads();
    if (t < 64) {
        int v = sb[t];
        int incl = v;
#pragma unroll
        for (int o = 1; o < 64; o <<= 1) {
            int n = (t >= o) ? sb[t - o] : 0;
            __syncthreads();
            incl += n;
            sb[t] = incl;
            __syncthreads();
        }
        sb[t] = incl - v;   // exclusive prefix
    } else {
#pragma unroll
        for (int o = 1; o < 64; o <<= 1) { __syncthreads(); __syncthreads(); }
    }
    __syncthreads();
    int i = blockIdx.x * blockDim.x + t;
    if (i < N_NODES) {
        int off = g_lex[i] + sb[i >> 10];
        g_off[i] = off;
        g_cur[i] = off;
    }
    if (i == 0) g_off[N_NODES] = N_EDGES;
}

// ---------------- fused per-edge score + CSR scatter ----------------
// 2 lanes per edge, 4 independent float4 loads per lane (MLP=4).
#define DOT4(A, B) ((A).x*(B).x + (A).y*(B).y + (A).z*(B).z + (A).w*(B).w)

__global__ __launch_bounds__(256) void edge_fused_kernel(const float* __restrict__ efeats,
                                                         const float* __restrict__ Wattn,
                                                         const int* __restrict__ src,
                                                         const int* __restrict__ dst) {
    int gid = blockIdx.x * blockDim.x + threadIdx.x;
    int e = gid >> 1;
    int l = gid & 1;
    if (e >= N_EDGES) return;
    const float* erow = &efeats[e * EDIM + l * 16];
    float4 ev0 = *(const float4*)&erow[0];
    float4 ev1 = *(const float4*)&erow[4];
    float4 ev2 = *(const float4*)&erow[8];
    float4 ev3 = *(const float4*)&erow[12];
    const float* arow = &Wattn[DIM + l * 16];
    float4 av0 = *(const float4*)&arow[0];
    float4 av1 = *(const float4*)&arow[4];
    float4 av2 = *(const float4*)&arow[8];
    float4 av3 = *(const float4*)&arow[12];
    float p = DOT4(ev0, av0) + DOT4(ev1, av1) + DOT4(ev2, av2) + DOT4(ev3, av3);
    p += __shfl_xor_sync(0xffffffffu, p, 1);
    if (l == 0) {
        int s = src[e];
        int d = dst[e];
        float t = p + g_ssrc[s];
        int pos = atomicAdd(&g_cur[d], 1);
        g_pair[pos] = make_uint2((unsigned)s, __float_as_uint(t));
    }
}

// ---------------- warp-per-node single-pass softmax + aggregation -------------
// Lanes 0-15 process even edges, 16-31 odd edges; each lane owns 8 dims (16B load).
__device__ __forceinline__ void fma8(float* acc, float a, uint4 r) {
    __half2* hp = (__half2*)&r;
#pragma unroll
    for (int i = 0; i < 4; i++) {
        float2 f = __half22float2(hp[i]);
        acc[2 * i]     += a * f.x;
        acc[2 * i + 1] += a * f.y;
    }
}

__global__ __launch_bounds__(256) void aggregate_kernel(float* __restrict__ h) {
    int gid = blockIdx.x * blockDim.x + threadIdx.x;
    int node = gid >> 5;
    int lane = gid & 31;
    if (node >= N_NODES) return;

    int beg = g_off[node];
    int end = g_off[node + 1];

    int half = lane >> 4;      // which edge of the pair this lane serves
    int sub  = lane & 15;      // dim group: dims sub*8 .. sub*8+7

    float acc[8];
#pragma unroll
    for (int i = 0; i < 8; i++) acc[i] = 0.f;
    float lsum = 0.f;

    if (beg < end) {
        float sd = g_sdst[node];

        for (int j0 = beg; j0 < end; j0 += 32) {
            int j = j0 + lane;
            float wgt = 0.f;
            int sidx = 0;
            if (j < end) {
                uint2 pr = g_pair[j];
                float x = __uint_as_float(pr.y) + sd;
                x = x > 0.f ? x : 0.01f * x;
                wgt = __expf(x);
                sidx = (int)pr.x;
            }
            lsum += wgt;
            int cnt = end - j0;
            if (cnt > 32) cnt = 32;
            // 4 edges per iteration: pair (q,q+1) on the two halves, and (q+2,q+3).
            // Out-of-range sources carry wgt=0 -> harmless row-0 reads.
            for (int q = 0; q < cnt; q += 4) {
                int e0 = q + half, e1 = q + 2 + half;
                float a0 = __shfl_sync(0xffffffffu, wgt, e0);
                float a1 = __shfl_sync(0xffffffffu, wgt, e1);
                int s0 = __shfl_sync(0xffffffffu, sidx, e0);
                int s1 = __shfl_sync(0xffffffffu, sidx, e1);
                uint4 r0 = *(const uint4*)&g_zh[s0 * 128 + sub * 8];
                uint4 r1 = *(const uint4*)&g_zh[s1 * 128 + sub * 8];
                fma8(acc, a0, r0);
                fma8(acc, a1, r1);
            }
        }

        // combine the two halves (each covered different edges, same dims)
#pragma unroll
        for (int i = 0; i < 8; i++)
            acc[i] += __shfl_xor_sync(0xffffffffu, acc[i], 16);

#pragma unroll
        for (int o = 16; o; o >>= 1) lsum += __shfl_xor_sync(0xffffffffu, lsum, o);
        float inv = 1.0f / lsum;
#pragma unroll
        for (int i = 0; i < 8; i++) acc[i] *= inv;
    }

    if (lane < 16) {
        float* orow = &h[node * 128 + sub * 8];
        *(float4*)&orow[0] = make_float4(acc[0], acc[1], acc[2], acc[3]);
        *(float4*)&orow[4] = make_float4(acc[4], acc[5], acc[6], acc[7]);
    }
}

// ---------------- launcher ----------------
extern "C" void kernel_launch(void* const* d_in, const int* in_sizes, int n_in,
                              void* d_out, int out_size) {
    const float* nfeats = (const float*)d_in[0];
    const float* efeats = (const float*)d_in[1];
    const float* W_fc   = (const float*)d_in[2];
    const float* W_attn = (const float*)d_in[3];
    const int*   src    = (const int*)d_in[4];
    const int*   dst    = (const int*)d_in[5];
    float* out = (float*)d_out;

    cudaFuncSetAttribute(gemm_mma_kernel, cudaFuncAttributeMaxDynamicSharedMemorySize,
                         SMG_TOTAL);

    gemm_mma_kernel<<<(N_NODES + 63) / 64, 256, SMG_TOTAL>>>(nfeats, W_fc, W_attn);
    hist_kernel<<<(N_EDGES / 8 + 255) / 256, 256>>>(dst);
    scan1_kernel<<<NB_SCAN, 1024>>>();
    scan23_kernel<<<(N_NODES + 255) / 256, 256>>>();
    edge_fused_kernel<<<(N_EDGES * 2 + 255) / 256, 256>>>(efeats, W_attn, src, dst);
    aggregate_kernel<<<(N_NODES * 32 + 255) / 256, 256>>>(out);
}

// round 14
// speedup vs baseline: 1.0374x; 1.0374x over previous
#include <cuda_runtime.h>
#include <cuda_bf16.h>
#include <cuda_fp16.h>
#include <math.h>
#include <float.h>
#include <stdint.h>

#define N_NODES 50000
#define N_EDGES 800000
#define DIM 128
#define EDIM 32
#define NB_SCAN ((N_NODES + 1023) / 1024)   // 49 scan blocks

// ---------------- scratch (static device allocations) ----------------
__device__ __half g_zh[N_NODES * DIM];    // projected features (fp16 for gather BW)
__device__ float g_ssrc[N_NODES];
__device__ float g_sdst[N_NODES];
__device__ int   g_cnt[N_NODES];          // zero-init at load; scan restores zeros
__device__ int   g_bsum[64];
__device__ int   g_off[N_NODES + 1];
__device__ int   g_cur[N_NODES];
__device__ uint2 g_pair[N_EDGES];         // (src, bits(t)) permuted into CSR-by-dst order
__device__ int   g_bar = 0;               // grid barrier counters (reset each replay)
__device__ int   g_bar2 = 0;

// ============ manual mma.sync bf16 GEMM: z = nfeats @ W_fc^T ==================
// 2-split, 3 passes (AhWh + AhWl + AlWh), fp32 accum; z stored fp16.
// Block: 256 threads (8 warps) = 64 rows x 128 cols. Warp w: n0 = w*16.
// Tail: each block histograms its 1024-edge slice of dst (overlaps MMA waves).
#define APAD 136           // bf16 row pad (272B rows: conflict-free ldmatrix)
#define WPAD 136
#define ZPAD 132           // f32 row pad for epilogue tile
#define SMG_AH   0
#define SMG_AL   17408                          // 64*136*2
#define SMG_WH   34816
#define SMG_WL   (34816 + 34816)                // 69632  (128*136*2 each)
#define SMG_ATTN 104448
#define SMG_TOTAL (SMG_ATTN + 256 * 4)          // 105472
#define SMG_ZT   0                              // f32 z tile overlays A after MMA

#define LDSM4(R, addr) \
    asm volatile("ldmatrix.sync.aligned.m8n8.x4.shared.b16 {%0,%1,%2,%3}, [%4];" \
        : "=r"((R)[0]), "=r"((R)[1]), "=r"((R)[2]), "=r"((R)[3]) : "r"(addr))

#define MMA_BF16(C, AR, B0, B1) \
    asm volatile("mma.sync.aligned.m16n8k16.row.col.f32.bf16.bf16.f32 " \
        "{%0,%1,%2,%3}, {%4,%5,%6,%7}, {%8,%9}, {%0,%1,%2,%3};" \
        : "+f"((C)[0]), "+f"((C)[1]), "+f"((C)[2]), "+f"((C)[3]) \
        : "r"((AR)[0]), "r"((AR)[1]), "r"((AR)[2]), "r"((AR)[3]), "r"(B0), "r"(B1))

__device__ __forceinline__ void split_store(__nv_bfloat16* sh, __nv_bfloat16* sl,
                                            int off, float4 v) {
    float f[4] = {v.x, v.y, v.z, v.w};
    uint16_t hh[4], ll[4];
#pragma unroll
    for (int q = 0; q < 4; q++) {
        __nv_bfloat16 h = __float2bfloat16(f[q]);
        hh[q] = __bfloat16_as_ushort(h);
        ll[q] = __bfloat16_as_ushort(__float2bfloat16(f[q] - __bfloat162float(h)));
    }
    *(uint2*)&sh[off] = make_uint2((uint32_t)hh[0] | ((uint32_t)hh[1] << 16),
                                   (uint32_t)hh[2] | ((uint32_t)hh[3] << 16));
    *(uint2*)&sl[off] = make_uint2((uint32_t)ll[0] | ((uint32_t)ll[1] << 16),
                                   (uint32_t)ll[2] | ((uint32_t)ll[3] << 16));
}

__global__ void __launch_bounds__(256) gemm_mma_kernel(const float* __restrict__ A,
                                                       const float* __restrict__ W,
                                                       const float* __restrict__ Wattn,
                                                       const int* __restrict__ dst) {
    extern __shared__ char smem[];
    __nv_bfloat16* sAh = (__nv_bfloat16*)(smem + SMG_AH);
    __nv_bfloat16* sAl = (__nv_bfloat16*)(smem + SMG_AL);
    __nv_bfloat16* sWh = (__nv_bfloat16*)(smem + SMG_WH);
    __nv_bfloat16* sWl = (__nv_bfloat16*)(smem + SMG_WL);
    float* szt  = (float*)(smem + SMG_ZT);
    float* asrc = (float*)(smem + SMG_ATTN);
    float* adst = asrc + 128;

    int tid = threadIdx.x;
    int wid = tid >> 5, lane = tid & 31;
    int i0 = blockIdx.x * 64;
    int n0 = wid * 16;

    if (tid < 128) {
        asrc[tid] = Wattn[tid];
        adst[tid] = Wattn[DIM + EDIM + tid];
    }

    // stage W fp32 -> split bf16 hi/lo into smem (W is L2-hot, 64 KB)
#pragma unroll
    for (int t = 0; t < 16; t++) {
        int idx = tid + t * 256;            // 4096 float4
        int row = idx >> 5, col = (idx & 31) * 4;
        float4 wv = *(const float4*)&W[row * 128 + col];
        split_store(sWh, sWl, row * WPAD + col, wv);
    }

    // load A 64x128 fp32, split to bf16 hi/lo in smem
#pragma unroll
    for (int t = 0; t < 8; t++) {
        int idx = tid + t * 256;            // 2048 float4
        int row = idx >> 5, col = (idx & 31) * 4;
        int gr = i0 + row;
        float4 av = make_float4(0.f, 0.f, 0.f, 0.f);
        if (gr < N_NODES) av = *(const float4*)&A[gr * 128 + col];
        split_store(sAh, sAl, row * APAD + col, av);
    }
    __syncthreads();

    uint32_t sb = (uint32_t)__cvta_generic_to_shared(smem);
    uint32_t aoff = (uint32_t)(((lane & 15) * APAD + (lane >> 4) * 8) * 2);
    uint32_t aH = sb + SMG_AH + aoff;
    uint32_t aL = sb + SMG_AL + aoff;
    uint32_t boff = (uint32_t)(((n0 + ((lane >> 4) << 3) + (lane & 7)) * WPAD
                                + (((lane >> 3) & 1) << 3)) * 2);
    uint32_t bH = sb + SMG_WH + boff;
    uint32_t bL = sb + SMG_WL + boff;

    float c[4][2][4];
#pragma unroll
    for (int m = 0; m < 4; m++)
#pragma unroll
        for (int g = 0; g < 2; g++)
#pragma unroll
            for (int q = 0; q < 4; q++) c[m][g][q] = 0.f;

#pragma unroll
    for (int pass = 0; pass < 3; pass++) {
        uint32_t ab = (pass == 2) ? aL : aH;
        uint32_t bb = (pass == 1) ? bL : bH;
#pragma unroll
        for (int k = 0; k < 8; k++) {
            uint32_t br[4];
            LDSM4(br, bb + k * 32);
#pragma unroll
            for (int m = 0; m < 4; m++) {
                uint32_t ar[4];
                LDSM4(ar, ab + (uint32_t)((m * 16 * APAD + k * 16) * 2));
                MMA_BF16(c[m][0], ar, br[0], br[1]);
                MMA_BF16(c[m][1], ar, br[2], br[3]);
            }
        }
    }

    __syncthreads();   // all warps done reading sA before z-tile overlay

#pragma unroll
    for (int m = 0; m < 4; m++)
#pragma unroll
        for (int g = 0; g < 2; g++) {
            int row = m * 16 + (lane >> 2);
            int col = n0 + g * 8 + (lane & 3) * 2;
            *(float2*)&szt[row * ZPAD + col] = make_float2(c[m][g][0], c[m][g][1]);
            *(float2*)&szt[(row + 8) * ZPAD + col] = make_float2(c[m][g][2], c[m][g][3]);
        }
    __syncthreads();

    // s_src / s_dst: thread t -> row t>>2, quarter t&3 (32 cols), 4-lane reduce
    {
        int r = tid >> 2, q = tid & 3;
        const float* zr = szt + r * ZPAD + q * 32;
        float ps = 0.f, pd = 0.f;
#pragma unroll
        for (int cc = 0; cc < 32; cc++) {
            float v = zr[cc];
            ps += v * asrc[q * 32 + cc];
            pd += v * adst[q * 32 + cc];
        }
        ps += __shfl_xor_sync(0xffffffffu, ps, 1);
        pd += __shfl_xor_sync(0xffffffffu, pd, 1);
        ps += __shfl_xor_sync(0xffffffffu, ps, 2);
        pd += __shfl_xor_sync(0xffffffffu, pd, 2);
        int gr = i0 + r;
        if (q == 0 && gr < N_NODES) { g_ssrc[gr] = ps; g_sdst[gr] = pd; }
    }

    // coalesced fp16 z store
#pragma unroll
    for (int t = 0; t < 8; t++) {
        int idx = tid + t * 256;
        int row = idx >> 5, col = (idx & 31) * 4;
        int gr = i0 + row;
        if (gr < N_NODES) {
            float4 v = *(const float4*)&szt[row * ZPAD + col];
            __half2 p0 = __floats2half2_rn(v.x, v.y);
            __half2 p1 = __floats2half2_rn(v.z, v.w);
            uint2 pk;
            pk.x = *(uint32_t*)&p0;
            pk.y = *(uint32_t*)&p1;
            *(uint2*)&g_zh[gr * 128 + col] = pk;
        }
    }

    // ---- histogram tail: this block's 1024-edge slice of dst ----
    // (N_EDGES % 4 == 0, so a bounds check on the int4 base suffices)
    {
        int ebase = blockIdx.x * 1024 + tid * 4;
        if (ebase < N_EDGES) {
            int4 d4 = *(const int4*)&dst[ebase];
            atomicAdd(&g_cnt[d4.x], 1);
            atomicAdd(&g_cnt[d4.y], 1);
            atomicAdd(&g_cnt[d4.z], 1);
            atomicAdd(&g_cnt[d4.w], 1);
        }
    }
}

// ---------------- merged scan: counts -> offsets, one launch ----------------
// 49 blocks x 1024 threads (all co-resident on 148 SMs -> grid barrier is safe).
// Two-counter barrier: g_bar arrives/spins; last g_bar2 finisher resets both,
// so every graph replay starts from zeroed counters (deterministic).
__global__ __launch_bounds__(1024) void scan_kernel() {
    __shared__ int ws[32];
    int t = threadIdx.x, b = blockIdx.x;
    int i = b * 1024 + t;
    int lane = t & 31, w = t >> 5;
    int c = (i < N_NODES) ? g_cnt[i] : 0;
    if (i < N_NODES) g_cnt[i] = 0;     // restore zeros for the next replay
    int v = c;
#pragma unroll
    for (int o = 1; o < 32; o <<= 1) {
        int n = __shfl_up_sync(0xffffffffu, v, o);
        if (lane >= o) v += n;
    }
    if (lane == 31) ws[w] = v;
    __syncthreads();
    if (w == 0) {
        int s = ws[lane];
#pragma unroll
        for (int o = 1; o < 32; o <<= 1) {
            int n = __shfl_up_sync(0xffffffffu, s, o);
            if (lane >= o) s += n;
        }
        ws[lane] = s;
    }
    __syncthreads();
    int pre = (w > 0) ? ws[w - 1] : 0;
    int lex = pre + v - c;             // block-local exclusive (kept in register)
    if (t == 0) {
        g_bsum[b] = ws[31];
        __threadfence();
        atomicAdd(&g_bar, 1);
        while (atomicAdd(&g_bar, 0) < NB_SCAN) { }   // spin until all arrived
    }
    __syncthreads();

    // block prefix: sum of g_bsum[0..b-1] (uniform loads, L2-hot)
    int bpre = 0;
    for (int k = 0; k < NB_SCAN; k++)
        if (k < b) bpre += g_bsum[k];

    if (i < N_NODES) {
        int off = lex + bpre;
        g_off[i] = off;
        g_cur[i] = off;
    }
    if (b == 0 && t == 0) g_off[N_NODES] = N_EDGES;

    __threadfence();
    __syncthreads();
    if (t == 0) {
        int d = atomicAdd(&g_bar2, 1);
        if (d == NB_SCAN - 1) { g_bar = 0; g_bar2 = 0; }   // reset for next replay
    }
}

// ---------------- fused per-edge score + CSR scatter ----------------
// 2 lanes per edge, 4 independent float4 loads per lane (MLP=4).
#define DOT4(A, B) ((A).x*(B).x + (A).y*(B).y + (A).z*(B).z + (A).w*(B).w)

__global__ __launch_bounds__(256) void edge_fused_kernel(const float* __restrict__ efeats,
                                                         const float* __restrict__ Wattn,
                                                         const int* __restrict__ src,
                                                         const int* __restrict__ dst) {
    int gid = blockIdx.x * blockDim.x + threadIdx.x;
    int e = gid >> 1;
    int l = gid & 1;
    if (e >= N_EDGES) return;
    const float* erow = &efeats[e * EDIM + l * 16];
    float4 ev0 = *(const float4*)&erow[0];
    float4 ev1 = *(const float4*)&erow[4];
    float4 ev2 = *(const float4*)&erow[8];
    float4 ev3 = *(const float4*)&erow[12];
    const float* arow = &Wattn[DIM + l * 16];
    float4 av0 = *(const float4*)&arow[0];
    float4 av1 = *(const float4*)&arow[4];
    float4 av2 = *(const float4*)&arow[8];
    float4 av3 = *(const float4*)&arow[12];
    float p = DOT4(ev0, av0) + DOT4(ev1, av1) + DOT4(ev2, av2) + DOT4(ev3, av3);
    p += __shfl_xor_sync(0xffffffffu, p, 1);
    if (l == 0) {
        int s = src[e];
        int d = dst[e];
        float t = p + g_ssrc[s];
        int pos = atomicAdd(&g_cur[d], 1);
        g_pair[pos] = make_uint2((unsigned)s, __float_as_uint(t));
    }
}

// ---------------- warp-per-node single-pass softmax + aggregation -------------
// Lanes 0-15 process even edges, 16-31 odd edges; each lane owns 8 dims (16B load).
__device__ __forceinline__ void fma8(float* acc, float a, uint4 r) {
    __half2* hp = (__half2*)&r;
#pragma unroll
    for (int i = 0; i < 4; i++) {
        float2 f = __half22float2(hp[i]);
        acc[2 * i]     += a * f.x;
        acc[2 * i + 1] += a * f.y;
    }
}

__global__ __launch_bounds__(256) void aggregate_kernel(float* __restrict__ h) {
    int gid = blockIdx.x * blockDim.x + threadIdx.x;
    int node = gid >> 5;
    int lane = gid & 31;
    if (node >= N_NODES) return;

    int beg = g_off[node];
    int end = g_off[node + 1];

    int half = lane >> 4;      // which edge of the pair this lane serves
    int sub  = lane & 15;      // dim group: dims sub*8 .. sub*8+7

    float acc[8];
#pragma unroll
    for (int i = 0; i < 8; i++) acc[i] = 0.f;
    float lsum = 0.f;

    if (beg < end) {
        float sd = g_sdst[node];

        for (int j0 = beg; j0 < end; j0 += 32) {
            int j = j0 + lane;
            float wgt = 0.f;
            int sidx = 0;
            if (j < end) {
                uint2 pr = g_pair[j];
                float x = __uint_as_float(pr.y) + sd;
                x = x > 0.f ? x : 0.01f * x;
                wgt = __expf(x);
                sidx = (int)pr.x;
            }
            lsum += wgt;
            int cnt = end - j0;
            if (cnt > 32) cnt = 32;
            // 4 edges per iteration across the two half-warps; OOR edges carry wgt=0.
            for (int q = 0; q < cnt; q += 4) {
                int e0 = q + half, e1 = q + 2 + half;
                float a0 = __shfl_sync(0xffffffffu, wgt, e0);
                float a1 = __shfl_sync(0xffffffffu, wgt, e1);
                int s0 = __shfl_sync(0xffffffffu, sidx, e0);
                int s1 = __shfl_sync(0xffffffffu, sidx, e1);
                uint4 r0 = *(const uint4*)&g_zh[s0 * 128 + sub * 8];
                uint4 r1 = *(const uint4*)&g_zh[s1 * 128 + sub * 8];
                fma8(acc, a0, r0);
                fma8(acc, a1, r1);
            }
        }

#pragma unroll
        for (int i = 0; i < 8; i++)
            acc[i] += __shfl_xor_sync(0xffffffffu, acc[i], 16);

#pragma unroll
        for (int o = 16; o; o >>= 1) lsum += __shfl_xor_sync(0xffffffffu, lsum, o);
        float inv = 1.0f / lsum;
#pragma unroll
        for (int i = 0; i < 8; i++) acc[i] *= inv;
    }

    if (lane < 16) {
        float* orow = &h[node * 128 + sub * 8];
        *(float4*)&orow[0] = make_float4(acc[0], acc[1], acc[2], acc[3]);
        *(float4*)&orow[4] = make_float4(acc[4], acc[5], acc[6], acc[7]);
    }
}

// ---------------- launcher (4 launches) ----------------
extern "C" void kernel_launch(void* const* d_in, const int* in_sizes, int n_in,
                              void* d_out, int out_size) {
    const float* nfeats = (const float*)d_in[0];
    const float* efeats = (const float*)d_in[1];
    const float* W_fc   = (const float*)d_in[2];
    const float* W_attn = (const float*)d_in[3];
    const int*   src    = (const int*)d_in[4];
    const int*   dst    = (const int*)d_in[5];
    float* out = (float*)d_out;

    cudaFuncSetAttribute(gemm_mma_kernel, cudaFuncAttributeMaxDynamicSharedMemorySize,
                         SMG_TOTAL);

    gemm_mma_kernel<<<(N_NODES + 63) / 64, 256, SMG_TOTAL>>>(nfeats, W_fc, W_attn, dst);
    scan_kernel<<<NB_SCAN, 1024>>>();
    edge_fused_kernel<<<(N_EDGES * 2 + 255) / 256, 256>>>(efeats, W_attn, src, dst);
    aggregate_kernel<<<(N_NODES * 32 + 255) / 256, 256>>>(out);
}